// round 2
// baseline (speedup 1.0000x reference)
#include <cuda_runtime.h>

typedef unsigned long long u64;

#define H_      51
#define TSTEPS  512
#define BTOT    1024
#define NB      8                 // batch rows per block
#define NBLK    (BTOT / NB)       // 128 blocks
#define NTHR    256
#define GP_     224               // padded gate count (204 -> 224 = 7*32)
#define L1K4    13                // layer1 K: 51 -> 52 -> 13 float4
#define L2K4    26                // layer2 K: 102 -> 104 -> 26 float4
#define HROW    108               // floats per batch h-row: [h1(51)|pad|h2(51)|pad|pad4]
#define GROW    232               // gate buffer row stride

// ---- shared memory layout (float offsets, all 16B aligned) ----
#define OFF_W1   0                         // [13][224][4]  = 11648
#define OFF_W2   (OFF_W1 + L1K4*GP_*4)     // [26][224][4]  = 23296
#define OFF_XS   (OFF_W2 + L2K4*GP_*4)     // 512*8         = 4096
#define OFF_HS   (OFF_XS + TSTEPS*NB)      // 8*108         = 864
#define OFF_C1   (OFF_HS + NB*HROW)        // 8*52
#define OFF_C2   (OFF_C1 + NB*52)          // 8*52
#define OFF_GB   (OFF_C2 + NB*52)          // 8*232
#define OFF_B1   (OFF_GB + NB*GROW)        // 224
#define OFF_B2   (OFF_B1 + GP_)            // 224
#define OFF_WI1  (OFF_B2 + GP_)            // 224
#define OFF_WL   (OFF_WI1 + GP_)           // 52
#define OFF_BL   (OFF_WL + 52)             // 4
#define SMEM_FLOATS (OFF_BL + 4)
#define SMEM_BYTES  (SMEM_FLOATS * 4)      // ~173 KB

__device__ __forceinline__ void ffma2(u64 &d, u64 a, u64 b) {
    // packed 2xfp32 fma: d.lo += a.lo*b.lo ; d.hi += a.hi*b.hi
    asm("fma.rn.f32x2 %0, %1, %2, %0;" : "+l"(d) : "l"(a), "l"(b));
}
__device__ __forceinline__ float2 unpk(u64 v) {
    float2 r;
    asm("mov.b64 {%0, %1}, %2;" : "=f"(r.x), "=f"(r.y) : "l"(v));
    return r;
}
__device__ __forceinline__ float sigf(float x) {
    // overflow-safe: x -> -inf gives e = inf -> 0 ; accurate division
    float e = __expf(-x);
    return 1.0f / (1.0f + e);
}

// gate GEMV phase: thread (s=tid>>3, b=tid&7) computes gates g = s + 32*j.
// Weights k-packed in smem: ulonglong2 at [kq][g] = W[g][4kq .. 4kq+3].
__device__ __forceinline__ void gate_phase(float* sm, int s, int b,
                                           int woff, int K4,
                                           int boff, bool hasx, float xv)
{
    const ulonglong2* __restrict__ wp =
        reinterpret_cast<const ulonglong2*>(sm + woff) + s;
    const ulonglong2* __restrict__ hp =
        reinterpret_cast<const ulonglong2*>(sm + OFF_HS + b * HROW);
    u64 acc[7];
#pragma unroll
    for (int j = 0; j < 7; j++) acc[j] = 0ull;

    if (K4 == L1K4) {
#pragma unroll
        for (int kq = 0; kq < L1K4; kq++) {
            ulonglong2 h = hp[kq];
#pragma unroll
            for (int j = 0; j < 7; j++) {
                ulonglong2 w = wp[kq * GP_ + 32 * j];
                ffma2(acc[j], w.x, h.x);
                ffma2(acc[j], w.y, h.y);
            }
        }
    } else {
#pragma unroll
        for (int kq = 0; kq < L2K4; kq++) {
            ulonglong2 h = hp[kq];
#pragma unroll
            for (int j = 0; j < 7; j++) {
                ulonglong2 w = wp[kq * GP_ + 32 * j];
                ffma2(acc[j], w.x, h.x);
                ffma2(acc[j], w.y, h.y);
            }
        }
    }

    float* gb = sm + OFF_GB + b * GROW;
#pragma unroll
    for (int j = 0; j < 7; j++) {
        int g = s + 32 * j;
        float2 p = unpk(acc[j]);
        float gv = p.x + p.y + sm[boff + g];
        if (hasx) gv = fmaf(xv, sm[OFF_WI1 + g], gv);
        gb[g] = gv;
    }
}

// pointwise LSTM cell update: 8 b * 51 j = 408 jobs over 256 threads (2 rounds)
__device__ __forceinline__ void update_phase(float* sm, int tid, int coff, int hoff)
{
#pragma unroll
    for (int r = 0; r < 2; r++) {
        int job = tid + r * NTHR;
        if (job < NB * H_) {
            int b = job & 7, j = job >> 3;       // j in 0..50
            const float* gb = sm + OFF_GB + b * GROW;
            float gi = gb[j];
            float gf = gb[H_ + j];
            float gg = gb[2 * H_ + j];
            float go = gb[3 * H_ + j];
            float c  = sm[coff + b * 52 + j];
            float cn = sigf(gf) * c + sigf(gi) * tanhf(gg);
            float hn = sigf(go) * tanhf(cn);
            sm[coff + b * 52 + j] = cn;
            sm[OFF_HS + b * HROW + hoff + j] = hn;
        }
    }
}

__global__ void __launch_bounds__(NTHR, 1)
lstm_kernel(const float* __restrict__ input,
            const float* __restrict__ Wih1, const float* __restrict__ Whh1,
            const float* __restrict__ bih1, const float* __restrict__ bhh1,
            const float* __restrict__ Wih2, const float* __restrict__ Whh2,
            const float* __restrict__ bih2, const float* __restrict__ bhh2,
            const float* __restrict__ Wlin, const float* __restrict__ blin,
            float* __restrict__ out)
{
    extern __shared__ float sm[];
    const int tid = threadIdx.x;
    const int bid = blockIdx.x;
    const int s = tid >> 3, b = tid & 7;

    // ---- staging ----
    for (int i = tid; i < NB * HROW; i += NTHR) sm[OFF_HS + i] = 0.0f;
    for (int i = tid; i < NB * 52 * 2; i += NTHR) sm[OFF_C1 + i] = 0.0f;

    for (int i = tid; i < TSTEPS * NB; i += NTHR) {
        int t = i >> 3, bb = i & 7;
        sm[OFF_XS + i] = input[t * BTOT + bid * NB + bb];
    }
    // W1: W_hh1 only (input term handled separately, IN=1)
    for (int i = tid; i < L1K4 * GP_ * 4; i += NTHR) {
        int c = i & 3, g = (i >> 2) % GP_, kq = i / (GP_ * 4);
        int k = 4 * kq + c;
        sm[OFF_W1 + i] = (g < 204 && k < H_) ? Whh1[g * H_ + k] : 0.0f;
    }
    // W2: concat [W_ih2 (k 0..50) | pad(51) | W_hh2 (k 52..102) | pad(103)]
    for (int i = tid; i < L2K4 * GP_ * 4; i += NTHR) {
        int c = i & 3, g = (i >> 2) % GP_, kq = i / (GP_ * 4);
        int k = 4 * kq + c;
        float v = 0.0f;
        if (g < 204) {
            if (k < H_)                 v = Wih2[g * H_ + k];
            else if (k >= 52 && k < 103) v = Whh2[g * H_ + (k - 52)];
        }
        sm[OFF_W2 + i] = v;
    }
    for (int i = tid; i < GP_; i += NTHR) {
        sm[OFF_B1  + i] = (i < 204) ? bih1[i] + bhh1[i] : 0.0f;
        sm[OFF_B2  + i] = (i < 204) ? bih2[i] + bhh2[i] : 0.0f;
        sm[OFF_WI1 + i] = (i < 204) ? Wih1[i] : 0.0f;
    }
    if (tid < 52) sm[OFF_WL + tid] = (tid < H_) ? Wlin[tid] : 0.0f;
    if (tid == 0) sm[OFF_BL] = blin[0];
    __syncthreads();

    // ---- recurrence ----
    for (int t = 0; t < TSTEPS; t++) {
        float xv = sm[OFF_XS + t * NB + b];
        gate_phase(sm, s, b, OFF_W1, L1K4, OFF_B1, true, xv);
        __syncthreads();
        update_phase(sm, tid, OFF_C1, 0);
        __syncthreads();
        gate_phase(sm, s, b, OFF_W2, L2K4, OFF_B2, false, 0.0f);
        __syncthreads();
        update_phase(sm, tid, OFF_C2, 52);
        __syncthreads();

        // output: out[b_global][t] = h2 . Wlin + blin  (warp 0 only)
        if (tid < 32) {
            int ob = tid & 7, part = tid >> 3;     // 4 parts x 13 k
            float a = 0.0f;
#pragma unroll
            for (int kk = 0; kk < 13; kk++) {
                int k = part * 13 + kk;            // k max 51 -> zero pad
                a = fmaf(sm[OFF_HS + ob * HROW + 52 + k], sm[OFF_WL + k], a);
            }
            a += __shfl_xor_sync(0xffffffffu, a, 8);
            a += __shfl_xor_sync(0xffffffffu, a, 16);
            if (tid < 8)
                out[(bid * NB + ob) * TSTEPS + t] = a + sm[OFF_BL];
        }
    }
}

extern "C" void kernel_launch(void* const* d_in, const int* in_sizes, int n_in,
                              void* d_out, int out_size)
{
    const float* input = (const float*)d_in[0];
    const float* Wih1  = (const float*)d_in[1];
    const float* Whh1  = (const float*)d_in[2];
    const float* bih1  = (const float*)d_in[3];
    const float* bhh1  = (const float*)d_in[4];
    const float* Wih2  = (const float*)d_in[5];
    const float* Whh2  = (const float*)d_in[6];
    const float* bih2  = (const float*)d_in[7];
    const float* bhh2  = (const float*)d_in[8];
    const float* Wlin  = (const float*)d_in[9];
    const float* blin  = (const float*)d_in[10];
    float* out = (float*)d_out;

    static bool attr_set = false;
    if (!attr_set) {
        cudaFuncSetAttribute(lstm_kernel,
                             cudaFuncAttributeMaxDynamicSharedMemorySize,
                             SMEM_BYTES);
        attr_set = true;
    }
    lstm_kernel<<<NBLK, NTHR, SMEM_BYTES>>>(input, Wih1, Whh1, bih1, bhh1,
                                            Wih2, Whh2, bih2, bhh2,
                                            Wlin, blin, out);
}

// round 3
// speedup vs baseline: 1.0470x; 1.0470x over previous
#include <cuda_runtime.h>

typedef unsigned long long u64;

#define H_      51
#define TSTEPS  512
#define BTOT    1024
#define NB      8                 // batch rows per block
#define NBLK    (BTOT / NB)       // 128 blocks
#define NTHR    512
#define GP_     224               // padded gate count (204 -> 224 = 7*32)
#define L1K4    13                // layer1 K: 51 -> 52 -> 13 float4
#define L2K4    26                // layer2 K: 102 -> 104 -> 26 float4
#define HROW    108               // floats per batch h-row: [h1(51)|pad|h2(51)|pad4]
#define GROW    232               // gate buffer row stride
#define GBH     (NB * GROW)       // offset between the two k-half gate buffers

// ---- shared memory layout (float offsets, all 16B aligned) ----
#define OFF_W1   0                         // [13][224][4]
#define OFF_W2   (OFF_W1 + L1K4*GP_*4)     // [26][224][4]
#define OFF_XS   (OFF_W2 + L2K4*GP_*4)     // 512*8
#define OFF_HS   (OFF_XS + TSTEPS*NB)      // 8*108
#define OFF_C1   (OFF_HS + NB*HROW)
#define OFF_C2   (OFF_C1 + NB*52)
#define OFF_GB   (OFF_C2 + NB*52)          // 2 * 8*232 (two k-halves)
#define OFF_B1   (OFF_GB + 2*GBH)
#define OFF_B2   (OFF_B1 + GP_)
#define OFF_WI1  (OFF_B2 + GP_)
#define OFF_WL   (OFF_WI1 + GP_)
#define OFF_BL   (OFF_WL + 52)
#define SMEM_FLOATS (OFF_BL + 4)
#define SMEM_BYTES  (SMEM_FLOATS * 4)      // ~180 KB

__device__ __forceinline__ void ffma2(u64 &d, u64 a, u64 b) {
    asm("fma.rn.f32x2 %0, %1, %2, %0;" : "+l"(d) : "l"(a), "l"(b));
}
__device__ __forceinline__ float2 unpk(u64 v) {
    float2 r;
    asm("mov.b64 {%0, %1}, %2;" : "=f"(r.x), "=f"(r.y) : "l"(v));
    return r;
}
__device__ __forceinline__ float sigf(float x) {
    float e = __expf(-x);
    return 1.0f / (1.0f + e);
}

// gate GEMV phase (one k-half): thread (s, b) computes gates g = s + 32*j.
// MODE 0: raw partial; 1: partial + bias; 2: partial + bias + x*Wih1.
template<int KQB, int KQE, int MODE>
__device__ __forceinline__ void gate_phase(float* sm, int s, int b,
                                           int woff, int boff,
                                           float xv, float* gb)
{
    const ulonglong2* __restrict__ wp =
        reinterpret_cast<const ulonglong2*>(sm + woff) + s;
    const ulonglong2* __restrict__ hp =
        reinterpret_cast<const ulonglong2*>(sm + OFF_HS + b * HROW);
    u64 acc[7];
#pragma unroll
    for (int j = 0; j < 7; j++) acc[j] = 0ull;
#pragma unroll
    for (int kq = KQB; kq < KQE; kq++) {
        ulonglong2 h = hp[kq];
#pragma unroll
        for (int j = 0; j < 7; j++) {
            ulonglong2 w = wp[kq * GP_ + 32 * j];
            ffma2(acc[j], w.x, h.x);
            ffma2(acc[j], w.y, h.y);
        }
    }
#pragma unroll
    for (int j = 0; j < 7; j++) {
        int g = s + 32 * j;
        float2 p = unpk(acc[j]);
        float gv = p.x + p.y;
        if (MODE >= 1) gv += sm[boff + g];
        if (MODE == 2) gv = fmaf(xv, sm[OFF_WI1 + g], gv);
        gb[g] = gv;
    }
}

// pointwise LSTM cell update: 408 jobs, one per thread; sums the two k-halves
__device__ __forceinline__ void update_phase(float* sm, int tid, int coff, int hoff)
{
    if (tid < NB * H_) {
        int b = tid & 7, j = tid >> 3;          // j in 0..50
        const float* gb0 = sm + OFF_GB + b * GROW;
        const float* gb1 = gb0 + GBH;
        float gi = gb0[j]          + gb1[j];
        float gf = gb0[H_ + j]     + gb1[H_ + j];
        float gg = gb0[2 * H_ + j] + gb1[2 * H_ + j];
        float go = gb0[3 * H_ + j] + gb1[3 * H_ + j];
        float c  = sm[coff + b * 52 + j];
        float cn = sigf(gf) * c + sigf(gi) * tanhf(gg);
        float hn = sigf(go) * tanhf(cn);
        sm[coff + b * 52 + j] = cn;
        sm[OFF_HS + b * HROW + hoff + j] = hn;
    }
}

__global__ void __launch_bounds__(NTHR, 1)
lstm_kernel(const float* __restrict__ input,
            const float* __restrict__ Wih1, const float* __restrict__ Whh1,
            const float* __restrict__ bih1, const float* __restrict__ bhh1,
            const float* __restrict__ Wih2, const float* __restrict__ Whh2,
            const float* __restrict__ bih2, const float* __restrict__ bhh2,
            const float* __restrict__ Wlin, const float* __restrict__ blin,
            float* __restrict__ out)
{
    extern __shared__ float sm[];
    const int tid = threadIdx.x;
    const int bid = blockIdx.x;
    const int b  = tid & 7;
    const int sk = tid >> 3;          // 0..63
    const int s  = sk & 31;           // gate slot 0..31
    const int kh = sk >> 5;           // k-half 0/1 (warps 0-7 vs 8-15)

    // ---- staging ----
    for (int i = tid; i < NB * HROW; i += NTHR) sm[OFF_HS + i] = 0.0f;
    for (int i = tid; i < NB * 52 * 2; i += NTHR) sm[OFF_C1 + i] = 0.0f;

    for (int i = tid; i < TSTEPS * NB; i += NTHR) {
        int t = i >> 3, bb = i & 7;
        sm[OFF_XS + i] = input[t * BTOT + bid * NB + bb];
    }
    // W1: W_hh1 only (input term handled separately, IN=1)
    for (int i = tid; i < L1K4 * GP_ * 4; i += NTHR) {
        int c = i & 3, g = (i >> 2) % GP_, kq = i / (GP_ * 4);
        int k = 4 * kq + c;
        sm[OFF_W1 + i] = (g < 204 && k < H_) ? Whh1[g * H_ + k] : 0.0f;
    }
    // W2: concat [W_ih2 (k 0..50) | pad(51) | W_hh2 (k 52..102) | pad(103)]
    for (int i = tid; i < L2K4 * GP_ * 4; i += NTHR) {
        int c = i & 3, g = (i >> 2) % GP_, kq = i / (GP_ * 4);
        int k = 4 * kq + c;
        float v = 0.0f;
        if (g < 204) {
            if (k < H_)                  v = Wih2[g * H_ + k];
            else if (k >= 52 && k < 103) v = Whh2[g * H_ + (k - 52)];
        }
        sm[OFF_W2 + i] = v;
    }
    for (int i = tid; i < GP_; i += NTHR) {
        sm[OFF_B1  + i] = (i < 204) ? bih1[i] + bhh1[i] : 0.0f;
        sm[OFF_B2  + i] = (i < 204) ? bih2[i] + bhh2[i] : 0.0f;
        sm[OFF_WI1 + i] = (i < 204) ? Wih1[i] : 0.0f;
    }
    if (tid < 52) sm[OFF_WL + tid] = (tid < H_) ? Wlin[tid] : 0.0f;
    if (tid == 0) sm[OFF_BL] = blin[0];
    __syncthreads();

    float* gb = sm + OFF_GB + kh * GBH + b * GROW;

    // ---- recurrence ----
    for (int t = 0; t < TSTEPS; t++) {
        float xv = sm[OFF_XS + t * NB + b];

        // layer 1 gates (h1 lives at HS offset 0, k = 0..51)
        if (kh == 0)
            gate_phase<0, 7, 2>(sm, s, b, OFF_W1, OFF_B1, xv, gb);
        else
            gate_phase<7, L1K4, 0>(sm, s, b, OFF_W1, 0, 0.0f, gb);
        __syncthreads();
        update_phase(sm, tid, OFF_C1, 0);
        __syncthreads();

        // layer 2 gates (input = concat(h1 | h2) at HS, k = 0..103)
        if (kh == 0)
            gate_phase<0, 13, 1>(sm, s, b, OFF_W2, OFF_B2, 0.0f, gb);
        else
            gate_phase<13, L2K4, 0>(sm, s, b, OFF_W2, 0, 0.0f, gb);
        __syncthreads();
        update_phase(sm, tid, OFF_C2, 52);
        __syncthreads();

        // output: out[b_global][t] = h2 . Wlin + blin  (warp 0 only)
        if (tid < 32) {
            int ob = tid & 7, part = tid >> 3;     // 4 parts x 13 k
            float a = 0.0f;
#pragma unroll
            for (int kk = 0; kk < 13; kk++) {
                int k = part * 13 + kk;            // k max 51 -> zero pad
                a = fmaf(sm[OFF_HS + ob * HROW + 52 + k], sm[OFF_WL + k], a);
            }
            a += __shfl_xor_sync(0xffffffffu, a, 8);
            a += __shfl_xor_sync(0xffffffffu, a, 16);
            if (tid < 8)
                out[(bid * NB + ob) * TSTEPS + t] = a + sm[OFF_BL];
        }
    }
}

extern "C" void kernel_launch(void* const* d_in, const int* in_sizes, int n_in,
                              void* d_out, int out_size)
{
    const float* input = (const float*)d_in[0];
    const float* Wih1  = (const float*)d_in[1];
    const float* Whh1  = (const float*)d_in[2];
    const float* bih1  = (const float*)d_in[3];
    const float* bhh1  = (const float*)d_in[4];
    const float* Wih2  = (const float*)d_in[5];
    const float* Whh2  = (const float*)d_in[6];
    const float* bih2  = (const float*)d_in[7];
    const float* bhh2  = (const float*)d_in[8];
    const float* Wlin  = (const float*)d_in[9];
    const float* blin  = (const float*)d_in[10];
    float* out = (float*)d_out;

    static bool attr_set = false;
    if (!attr_set) {
        cudaFuncSetAttribute(lstm_kernel,
                             cudaFuncAttributeMaxDynamicSharedMemorySize,
                             SMEM_BYTES);
        attr_set = true;
    }
    lstm_kernel<<<NBLK, NTHR, SMEM_BYTES>>>(input, Wih1, Whh1, bih1, bhh1,
                                            Wih2, Whh2, bih2, bhh2,
                                            Wlin, blin, out);
}